// round 10
// baseline (speedup 1.0000x reference)
#include <cuda_runtime.h>
#include <cuda_fp16.h>
#include <stdint.h>
#include <math.h>

#define BD    4
#define NSEQ  1024
#define DM    256
#define NH    8
#define HD    32
#define DFFN  1024
#define MROWS (BD * NSEQ)   // 4096

// ---------------- static scratch ----------------
__device__ float  g_qkin[MROWS * DM];        // embed + query_pos
__device__ __half g_qkh[MROWS * 512];        // [4096, 512]: q|k fp16 (q pre-scaled)
__device__ __half g_vth[BD * DM * NSEQ];     // [B, 256 d, 1024 j]: V transposed fp16
__device__ float  g_tau[BD * NH * NSEQ];     // [B, H, N]
__device__ float  g_ctx[MROWS * DM];
__device__ float  g_y[MROWS * DM];
__device__ float  g_x[MROWS * DM];
__device__ float  g_h[MROWS * DFFN];

// ---------------- helpers ----------------
__device__ __forceinline__ void cp16(float* dst, const float* src)
{
    unsigned d = (unsigned)__cvta_generic_to_shared(dst);
    asm volatile("cp.async.cg.shared.global [%0], [%1], 16;" :: "r"(d), "l"(src));
}
__device__ __forceinline__ void cp16h(__half* dst, const __half* src)
{
    unsigned d = (unsigned)__cvta_generic_to_shared(dst);
    asm volatile("cp.async.cg.shared.global [%0], [%1], 16;" :: "r"(d), "l"(src));
}
#define CP_COMMIT() asm volatile("cp.async.commit_group;")

#define MMA_TF32(d, a, b0, b1)                                              \
    asm volatile("mma.sync.aligned.m16n8k8.row.col.f32.tf32.tf32.f32 "      \
                 "{%0,%1,%2,%3}, {%4,%5,%6,%7}, {%8,%9}, {%0,%1,%2,%3};"    \
                 : "+f"((d)[0]), "+f"((d)[1]), "+f"((d)[2]), "+f"((d)[3])   \
                 : "r"((a)[0]), "r"((a)[1]), "r"((a)[2]), "r"((a)[3]),      \
                   "r"(b0), "r"(b1))

#define MMA_F16(d, a, b0, b1)                                               \
    asm volatile("mma.sync.aligned.m16n8k16.row.col.f32.f16.f16.f32 "       \
                 "{%0,%1,%2,%3}, {%4,%5,%6,%7}, {%8,%9}, {%0,%1,%2,%3};"    \
                 : "+f"((d)[0]), "+f"((d)[1]), "+f"((d)[2]), "+f"((d)[3])   \
                 : "r"((a)[0]), "r"((a)[1]), "r"((a)[2]), "r"((a)[3]),      \
                   "r"(b0), "r"(b1))

__device__ __forceinline__ unsigned packh2(float lo, float hi)
{
    __half2 h = __floats2half2_rn(lo, hi);
    return *reinterpret_cast<unsigned*>(&h);
}

// ---------------- elementwise: qk = embed + query_pos ----------------
__global__ void add_pos_kernel(const float4* __restrict__ a,
                               const float4* __restrict__ b,
                               float4* __restrict__ o)
{
    int i = blockIdx.x * blockDim.x + threadIdx.x;
    float4 x = a[i], y = b[i];
    o[i] = make_float4(x.x + y.x, x.y + y.y, x.z + y.z, x.w + y.w);
}

// ---------------- tau ----------------
__global__ void tau_kernel(const float* __restrict__ embed,
                           const float* __restrict__ tw,
                           const float* __restrict__ tb,
                           float* __restrict__ tau)
{
    int warp_id = (blockIdx.x * blockDim.x + threadIdx.x) >> 5;
    int lane = threadIdx.x & 31;
    const float* er = embed + (size_t)warp_id * DM;
    float ph[NH];
    #pragma unroll
    for (int h = 0; h < NH; h++) ph[h] = 0.f;
    #pragma unroll
    for (int t = 0; t < 8; t++) {
        int d = lane + t * 32;
        float e = er[d];
        #pragma unroll
        for (int h = 0; h < NH; h++) ph[h] += e * tw[h * DM + d];
    }
    #pragma unroll
    for (int h = 0; h < NH; h++) {
        float v = ph[h];
        #pragma unroll
        for (int o = 16; o > 0; o >>= 1) v += __shfl_xor_sync(0xffffffffu, v, o);
        if (lane == 0) {
            int b = warp_id >> 10, n = warp_id & 1023;
            tau[((size_t)b * NH + h) * NSEQ + n] = v + tb[h];
        }
    }
}

// ---------------- async tile loader for GEMM ----------------
template<int BM>
__device__ __forceinline__ void gemm_load(const float* __restrict__ Ag,
                                          const float* __restrict__ Wg,
                                          float* sA, float* sB, int tid, int K)
{
    constexpr int T = BM * 2;
    #pragma unroll
    for (int i = 0; i < (BM * 8) / T; i++) {
        int idx = tid + i * T;
        int row = idx >> 3, c4 = (idx & 7) << 2;
        cp16(sA + row * 36 + c4, Ag + (size_t)row * K + c4);
    }
    #pragma unroll
    for (int i = 0; i < 512 / T; i++) {
        int idx = tid + i * T;
        int row = idx >> 3, c4 = (idx & 7) << 2;
        cp16(sB + row * 36 + c4, Wg + (size_t)row * K + c4);
    }
    CP_COMMIT();
}

// ---------------- tf32 tensor-core GEMM (double-buffered cp.async) ----------------
// C[M,N] = A[M,K] @ W[N,K]^T + bias (+relu)(+resid)
// Output: Cf (f32) or Ch (fp16). biasRow: bias indexed by row. scaleLim/scaleVal:
// multiply result by scaleVal for global cols < scaleLim. zW/zC: z-batch strides.
template<int BM>
__global__ void gemm_tc(const float* __restrict__ A, const float* __restrict__ W,
                        const float* __restrict__ bias, const float* __restrict__ resid,
                        float* __restrict__ Cf, __half* __restrict__ Ch,
                        int M, int N, int K, int doRelu, int biasRow,
                        int scaleLim, float scaleVal, size_t zW, size_t zC)
{
    extern __shared__ float smem[];
    constexpr int STAGE = (BM + 64) * 36;
    int tid = threadIdx.x, lane = tid & 31, wid = tid >> 5;
    int m0 = blockIdx.y * BM, n0 = blockIdx.x * 64;
    const float* Abase = A + (size_t)m0 * K;
    const float* Wbase = W + (size_t)blockIdx.z * zW + (size_t)n0 * K;
    int nk = K >> 5;

    constexpr int WMN = BM / 32;
    int wm = (wid % WMN) * 32, wn = (wid / WMN) * 32;
    int gr = lane >> 2, gq = lane & 3;

    gemm_load<BM>(Abase, Wbase, smem, smem + BM * 36, tid, K);

    float acc[2][4][4];
    #pragma unroll
    for (int mi = 0; mi < 2; mi++)
        #pragma unroll
        for (int ni = 0; ni < 4; ni++)
            #pragma unroll
            for (int k = 0; k < 4; k++) acc[mi][ni][k] = 0.f;

    for (int kt = 0; kt < nk; kt++) {
        float* cur = smem + (kt & 1) * STAGE;
        float* nxt = smem + ((kt + 1) & 1) * STAGE;
        if (kt + 1 < nk) {
            gemm_load<BM>(Abase + (kt + 1) * 32, Wbase + (kt + 1) * 32,
                          nxt, nxt + BM * 36, tid, K);
            asm volatile("cp.async.wait_group 1;");
        } else {
            asm volatile("cp.async.wait_group 0;");
        }
        __syncthreads();
        const float* cA = cur;
        const float* cB = cur + BM * 36;
        #pragma unroll
        for (int k0 = 0; k0 < 32; k0 += 8) {
            unsigned af[2][4], bf[4][2];
            #pragma unroll
            for (int mi = 0; mi < 2; mi++) {
                int r = wm + mi * 16 + gr, c = k0 + gq;
                af[mi][0] = __float_as_uint(cA[r * 36 + c]);
                af[mi][1] = __float_as_uint(cA[(r + 8) * 36 + c]);
                af[mi][2] = __float_as_uint(cA[r * 36 + c + 4]);
                af[mi][3] = __float_as_uint(cA[(r + 8) * 36 + c + 4]);
            }
            #pragma unroll
            for (int ni = 0; ni < 4; ni++) {
                int cc = wn + ni * 8 + gr;
                bf[ni][0] = __float_as_uint(cB[cc * 36 + k0 + gq]);
                bf[ni][1] = __float_as_uint(cB[cc * 36 + k0 + 4 + gq]);
            }
            #pragma unroll
            for (int mi = 0; mi < 2; mi++)
                #pragma unroll
                for (int ni = 0; ni < 4; ni++)
                    MMA_TF32(acc[mi][ni], af[mi], bf[ni][0], bf[ni][1]);
        }
        __syncthreads();
    }

    #pragma unroll
    for (int mi = 0; mi < 2; mi++) {
        #pragma unroll
        for (int ni = 0; ni < 4; ni++) {
            int r = m0 + wm + mi * 16 + gr;
            int c = n0 + wn + ni * 8 + 2 * gq;
            float v0 = acc[mi][ni][0], v1 = acc[mi][ni][1];
            float v2 = acc[mi][ni][2], v3 = acc[mi][ni][3];
            if (biasRow) {
                float bA = bias[r], bB = bias[r + 8];
                v0 += bA; v1 += bA; v2 += bB; v3 += bB;
            } else {
                float2 bb = *(const float2*)(bias + c);
                v0 += bb.x; v1 += bb.y; v2 += bb.x; v3 += bb.y;
            }
            if (doRelu) {
                v0 = fmaxf(v0, 0.f); v1 = fmaxf(v1, 0.f);
                v2 = fmaxf(v2, 0.f); v3 = fmaxf(v3, 0.f);
            }
            if (c < scaleLim) {
                v0 *= scaleVal; v1 *= scaleVal; v2 *= scaleVal; v3 *= scaleVal;
            }
            if (resid) {
                float2 r0v = *(const float2*)(resid + (size_t)r * N + c);
                float2 r1v = *(const float2*)(resid + (size_t)(r + 8) * N + c);
                v0 += r0v.x; v1 += r0v.y; v2 += r1v.x; v3 += r1v.y;
            }
            if (Ch) {
                __half* Cz = Ch + (size_t)blockIdx.z * zC;
                *(__half2*)(Cz + (size_t)r * N + c) = __floats2half2_rn(v0, v1);
                *(__half2*)(Cz + (size_t)(r + 8) * N + c) = __floats2half2_rn(v2, v3);
            } else {
                *(float2*)(Cf + (size_t)r * N + c) = make_float2(v0, v1);
                *(float2*)(Cf + (size_t)(r + 8) * N + c) = make_float2(v2, v3);
            }
        }
    }
}

// ---------------- attention smem geometry (fp16) ----------------
#define KHS 40                           // K/Q smem row stride in halves (32 data + pad)
#define VHS 72                           // VT smem row stride in halves (64 data + pad)
#define STG_H (64 * KHS + 32 * VHS)      // one stage = 4864 halves = 9728 B
#define OFF_STATB (2 * STG_H * 2)        // bytes: 19456
#define OFF_QB (OFF_STATB + 1024)        // Q staging: 20480
#define SMEM_ATT (OFF_QB + 64 * KHS * 2) // 25600 B

// loader: K tile 64 rows x 32 halves, VT tile 32 d-rows x 64 j-halves (256 thr)
__device__ __forceinline__ void attn_loadh(const __half* __restrict__ kg,
                                           const __half* __restrict__ vg,
                                           __half* stage, int tid)
{
    {
        int row = tid >> 2, seg = (tid & 3) * 8;
        cp16h(stage + row * KHS + seg, kg + (size_t)row * 512 + seg);
    }
    {
        int row = tid >> 3, seg = (tid & 7) * 8;
        cp16h(stage + 64 * KHS + row * VHS + seg, vg + (size_t)row * NSEQ + seg);
    }
    CP_COMMIT();
}

// ---------------- fp16 flash attention: 64 q-rows, 8 warps (4m x 2n) ----------------
// P never touches smem: S C-fragments repack directly into PV A-fragments.
__global__ __launch_bounds__(256, 3)
void attn_h(const __half* __restrict__ qkh, const __half* __restrict__ vth,
            const float* __restrict__ dist, const float* __restrict__ tau,
            float* __restrict__ ctx)
{
    extern __shared__ char smc[];
    float* pmax = (float*)(smc + OFF_STATB);   // [2][64]
    float* psum = pmax + 128;                  // [2][64]
    __half* Qs  = (__half*)(smc + OFF_QB);     // 64 x KHS

    int b = blockIdx.z, h = blockIdx.y, i0 = blockIdx.x * 64;
    int tid = threadIdx.x, lane = tid & 31, wid = tid >> 5;
    int wm = wid & 3, wn = wid >> 2;
    int gr = lane >> 2, gq = lane & 3;
    int wr = wm * 16;
    int r0 = wr + gr, r1 = r0 + 8;

    // ---- stage Q (fp16, pre-scaled by 1/sqrt(d) in the projection GEMM)
    {
        int row = tid >> 2, seg = (tid & 3) * 8;
        cp16h(Qs + row * KHS + seg,
              qkh + (size_t)(b * NSEQ + i0 + row) * 512 + h * 32 + seg);
        CP_COMMIT();
        asm volatile("cp.async.wait_group 0;");
        __syncthreads();
    }
    unsigned qf[2][4];
    #pragma unroll
    for (int c = 0; c < 2; c++) {
        int off = c * 16 + 2 * gq;
        qf[c][0] = *(const unsigned*)&Qs[r0 * KHS + off];
        qf[c][1] = *(const unsigned*)&Qs[r1 * KHS + off];
        qf[c][2] = *(const unsigned*)&Qs[r0 * KHS + off + 8];
        qf[c][3] = *(const unsigned*)&Qs[r1 * KHS + off + 8];
    }

    const __half* kg = qkh + (size_t)(b * NSEQ) * 512 + 256 + h * 32;
    const __half* vg = vth + ((size_t)b * DM + h * 32) * NSEQ;

    attn_loadh(kg, vg, (__half*)smc, tid);

    float tv0 = tau[((size_t)b * NH + h) * NSEQ + i0 + r0];
    float tv1 = tau[((size_t)b * NH + h) * NSEQ + i0 + r1];
    const float* dp0 = dist + ((size_t)b * NSEQ + i0 + r0) * NSEQ + wn * 32;
    const float* dp1 = dist + ((size_t)b * NSEQ + i0 + r1) * NSEQ + wn * 32;

    float mr0 = -1e30f, mr1 = -1e30f, lr0 = 0.f, lr1 = 0.f;
    float o[4][4];
    #pragma unroll
    for (int ni = 0; ni < 4; ni++)
        #pragma unroll
        for (int k = 0; k < 4; k++) o[ni][k] = 0.f;

    for (int jt = 0; jt < NSEQ / 64; jt++) {
        __half* cur = (__half*)smc + (jt & 1) * STG_H;
        __half* nxt = (__half*)smc + ((jt + 1) & 1) * STG_H;
        if (jt + 1 < NSEQ / 64) {
            attn_loadh(kg + (size_t)(jt + 1) * 64 * 512, vg + (jt + 1) * 64, nxt, tid);
            asm volatile("cp.async.wait_group 1;");
        } else {
            asm volatile("cp.async.wait_group 0;");
        }
        __syncthreads();                               // [S1] KV visible
        const __half* Ks  = cur;
        const __half* VTs = cur + 64 * KHS;

        // ---- S quadrant: rows wr.., cols wn*32.. (k=32 via 2 chunks of k16)
        float s[4][4];
        #pragma unroll
        for (int ni = 0; ni < 4; ni++)
            #pragma unroll
            for (int k = 0; k < 4; k++) s[ni][k] = 0.f;

        #pragma unroll
        for (int c = 0; c < 2; c++) {
            int koff = c * 16 + 2 * gq;
            unsigned bk[4][2];
            #pragma unroll
            for (int ni = 0; ni < 4; ni++) {
                int jr = wn * 32 + ni * 8 + gr;
                bk[ni][0] = *(const unsigned*)&Ks[jr * KHS + koff];
                bk[ni][1] = *(const unsigned*)&Ks[jr * KHS + koff + 8];
            }
            #pragma unroll
            for (int ni = 0; ni < 4; ni++)
                MMA_F16(s[ni], qf[c], bk[ni][0], bk[ni][1]);
        }

        // ---- bias + partial max
        float tm0 = -1e30f, tm1 = -1e30f;
        #pragma unroll
        for (int ni = 0; ni < 4; ni++) {
            int jc = jt * 64 + ni * 8 + 2 * gq;        // dp already offset by wn*32
            float2 dA = *(const float2*)(dp0 + jc);
            float2 dB = *(const float2*)(dp1 + jc);
            s[ni][0] += dA.x * tv0;
            s[ni][1] += dA.y * tv0;
            s[ni][2] += dB.x * tv1;
            s[ni][3] += dB.y * tv1;
            tm0 = fmaxf(tm0, fmaxf(s[ni][0], s[ni][1]));
            tm1 = fmaxf(tm1, fmaxf(s[ni][2], s[ni][3]));
        }
        tm0 = fmaxf(tm0, __shfl_xor_sync(0xffffffffu, tm0, 1));
        tm0 = fmaxf(tm0, __shfl_xor_sync(0xffffffffu, tm0, 2));
        tm1 = fmaxf(tm1, __shfl_xor_sync(0xffffffffu, tm1, 1));
        tm1 = fmaxf(tm1, __shfl_xor_sync(0xffffffffu, tm1, 2));
        if (gq == 0) {
            pmax[wn * 64 + r0] = tm0;
            pmax[wn * 64 + r1] = tm1;
        }
        __syncthreads();                               // [S2] stats half 1

        float mn0 = fmaxf(mr0, fmaxf(pmax[r0], pmax[64 + r0]));
        float mn1 = fmaxf(mr1, fmaxf(pmax[r1], pmax[64 + r1]));
        float cor0 = __expf(mr0 - mn0), cor1 = __expf(mr1 - mn1);
        mr0 = mn0; mr1 = mn1;

        float ps0 = 0.f, ps1 = 0.f;
        #pragma unroll
        for (int ni = 0; ni < 4; ni++) {
            s[ni][0] = __expf(s[ni][0] - mn0);
            s[ni][1] = __expf(s[ni][1] - mn0);
            s[ni][2] = __expf(s[ni][2] - mn1);
            s[ni][3] = __expf(s[ni][3] - mn1);
            ps0 += s[ni][0] + s[ni][1];
            ps1 += s[ni][2] + s[ni][3];
        }
        ps0 += __shfl_xor_sync(0xffffffffu, ps0, 1);
        ps0 += __shfl_xor_sync(0xffffffffu, ps0, 2);
        ps1 += __shfl_xor_sync(0xffffffffu, ps1, 1);
        ps1 += __shfl_xor_sync(0xffffffffu, ps1, 2);
        if (gq == 0) {
            psum[wn * 64 + r0] = ps0;
            psum[wn * 64 + r1] = ps1;
        }
        __syncthreads();                               // [S3] stats half 2

        lr0 = lr0 * cor0 + psum[r0] + psum[64 + r0];
        lr1 = lr1 * cor1 + psum[r1] + psum[64 + r1];
        #pragma unroll
        for (int ni = 0; ni < 4; ni++) {
            o[ni][0] *= cor0; o[ni][1] *= cor0;
            o[ni][2] *= cor1; o[ni][3] *= cor1;
        }

        // ---- pack P into PV A-fragments (no smem!)
        unsigned pf[2][4];
        #pragma unroll
        for (int c = 0; c < 2; c++) {
            pf[c][0] = packh2(s[2 * c][0],     s[2 * c][1]);
            pf[c][1] = packh2(s[2 * c][2],     s[2 * c][3]);
            pf[c][2] = packh2(s[2 * c + 1][0], s[2 * c + 1][1]);
            pf[c][3] = packh2(s[2 * c + 1][2], s[2 * c + 1][3]);
        }

        // ---- partial O += P[:, warp's 32-col strip] @ V[strip, :]
        #pragma unroll
        for (int c = 0; c < 2; c++) {
            int jo = wn * 32 + c * 16 + 2 * gq;
            unsigned bv[4][2];
            #pragma unroll
            for (int ni = 0; ni < 4; ni++) {
                int dr = ni * 8 + gr;
                bv[ni][0] = *(const unsigned*)&VTs[dr * VHS + jo];
                bv[ni][1] = *(const unsigned*)&VTs[dr * VHS + jo + 8];
            }
            #pragma unroll
            for (int ni = 0; ni < 4; ni++)
                MMA_F16(o[ni], pf[c], bv[ni][0], bv[ni][1]);
        }
        __syncthreads();                               // [S4] protect cur
    }

    // ---- combine the two k-half partial Os (Osum aliases stage smem)
    float* Osum = (float*)smc;                         // 64 x 33
    if (wn == 0) {
        #pragma unroll
        for (int ni = 0; ni < 4; ni++) {
            int d = ni * 8 + 2 * gq;
            Osum[r0 * 33 + d]     = o[ni][0];
            Osum[r0 * 33 + d + 1] = o[ni][1];
            Osum[r1 * 33 + d]     = o[ni][2];
            Osum[r1 * 33 + d + 1] = o[ni][3];
        }
    }
    __syncthreads();
    if (wn == 1) {
        float il0 = 1.f / lr0, il1 = 1.f / lr1;
        size_t gA = (size_t)(b * NSEQ + i0 + r0) * 256 + h * 32;
        size_t gB = (size_t)(b * NSEQ + i0 + r1) * 256 + h * 32;
        #pragma unroll
        for (int ni = 0; ni < 4; ni++) {
            int d = ni * 8 + 2 * gq;
            float a0 = (Osum[r0 * 33 + d]     + o[ni][0]) * il0;
            float a1 = (Osum[r0 * 33 + d + 1] + o[ni][1]) * il0;
            float a2 = (Osum[r1 * 33 + d]     + o[ni][2]) * il1;
            float a3 = (Osum[r1 * 33 + d + 1] + o[ni][3]) * il1;
            *(float2*)(ctx + gA + d) = make_float2(a0, a1);
            *(float2*)(ctx + gB + d) = make_float2(a2, a3);
        }
    }
}

// ---------------- row LayerNorm ----------------
__global__ void ln_kernel(const float* __restrict__ in, const float* __restrict__ g,
                          const float* __restrict__ bt, float* __restrict__ out)
{
    int row = blockIdx.x, t = threadIdx.x;
    float v = in[(size_t)row * DM + t];
    float s = v, s2 = v * v;
    #pragma unroll
    for (int o = 16; o > 0; o >>= 1) {
        s  += __shfl_xor_sync(0xffffffffu, s, o);
        s2 += __shfl_xor_sync(0xffffffffu, s2, o);
    }
    __shared__ float rs[8], rs2[8];
    __shared__ float mu_s, rstd_s;
    int w = t >> 5, lane = t & 31;
    if (lane == 0) { rs[w] = s; rs2[w] = s2; }
    __syncthreads();
    if (t == 0) {
        float a = 0.f, b2 = 0.f;
        #pragma unroll
        for (int i = 0; i < 8; i++) { a += rs[i]; b2 += rs2[i]; }
        float mu = a * (1.f / 256.f);
        float var = b2 * (1.f / 256.f) - mu * mu;
        mu_s = mu;
        rstd_s = rsqrtf(var + 1e-5f);
    }
    __syncthreads();
    out[(size_t)row * DM + t] = (v - mu_s) * rstd_s * g[t] + bt[t];
}

// ---------------- launch ----------------
static void* sym_addr(const void* sym)
{
    void* p = nullptr;
    cudaGetSymbolAddress(&p, sym);
    return p;
}

extern "C" void kernel_launch(void* const* d_in, const int* in_sizes, int n_in,
                              void* d_out, int out_size)
{
    const float* embed = (const float*)d_in[0];
    const float* dist  = (const float*)d_in[2];
    const float* qpos  = (const float*)d_in[3];
    const float* inw   = (const float*)d_in[4];
    const float* inb   = (const float*)d_in[5];
    const float* outw  = (const float*)d_in[6];
    const float* outb  = (const float*)d_in[7];
    const float* tauw  = (const float*)d_in[8];
    const float* taub  = (const float*)d_in[9];
    const float* w1    = (const float*)d_in[10];
    const float* b1    = (const float*)d_in[11];
    const float* w2    = (const float*)d_in[12];
    const float* b2    = (const float*)d_in[13];
    const float* g1    = (const float*)d_in[14];
    const float* be1   = (const float*)d_in[15];
    const float* g2    = (const float*)d_in[16];
    const float* be2   = (const float*)d_in[17];
    float* out = (float*)d_out;

    float*  qkin = (float*)sym_addr(g_qkin);
    __half* qkh  = (__half*)sym_addr(g_qkh);
    __half* vth  = (__half*)sym_addr(g_vth);
    float*  tau  = (float*)sym_addr(g_tau);
    float*  ctx  = (float*)sym_addr(g_ctx);
    float*  y    = (float*)sym_addr(g_y);
    float*  x    = (float*)sym_addr(g_x);
    float*  hbuf = (float*)sym_addr(g_h);

    const int smem128 = 2 * (128 + 64) * 36 * 4;   // 55296
    const int smem64  = 2 * (64 + 64) * 36 * 4;    // 36864
    const float sc = 0.17677669529663687f;         // 1/sqrt(32)

    cudaFuncSetAttribute(gemm_tc<128>, cudaFuncAttributeMaxDynamicSharedMemorySize, smem128);
    cudaFuncSetAttribute(gemm_tc<64>,  cudaFuncAttributeMaxDynamicSharedMemorySize, smem64);
    cudaFuncSetAttribute(attn_h,       cudaFuncAttributeMaxDynamicSharedMemorySize, SMEM_ATT);

    // 1) qk = embed + query_pos
    add_pos_kernel<<<(MROWS * DM / 4) / 256, 256>>>(
        (const float4*)embed, (const float4*)qpos, (float4*)qkin);

    // 2) tau
    tau_kernel<<<512, 256>>>(embed, tauw, taub, tau);

    // 3) q|k projection -> fp16 (q columns pre-scaled by 1/sqrt(d))
    gemm_tc<128><<<dim3(8, 32, 1), 256, smem128>>>(
        qkin, inw, inb, nullptr, nullptr, qkh,
        MROWS, 512, DM, 0, 0, 256, sc, 0, 0);

    // 4) V^T = wv @ embed^T per batch -> fp16 [B, 256, 1024] (row bias)
    gemm_tc<64><<<dim3(16, 4, BD), 128, smem64>>>(
        inw + 512 * DM, embed, inb + 512, nullptr, nullptr, vth,
        DM, NSEQ, DM, 0, 1, 0, 1.f,
        (size_t)NSEQ * DM, (size_t)DM * NSEQ);

    // 5) attention (fp16 mainloop, f32 accum)
    attn_h<<<dim3(NSEQ / 64, NH, BD), 256, SMEM_ATT>>>(qkh, vth, dist, tau, ctx);

    // 6) out projection + residual(embed)
    gemm_tc<64><<<dim3(4, 64, 1), 128, smem64>>>(
        ctx, outw, outb, embed, y, nullptr,
        MROWS, DM, DM, 0, 0, 0, 1.f, 0, 0);

    // 7) LN1
    ln_kernel<<<MROWS, 256>>>(y, g1, be1, x);

    // 8) FFN1 + ReLU
    gemm_tc<128><<<dim3(16, 32, 1), 256, smem128>>>(
        x, w1, b1, nullptr, hbuf, nullptr,
        MROWS, DFFN, DM, 1, 0, 0, 1.f, 0, 0);

    // 9) FFN2 + residual(x)
    gemm_tc<64><<<dim3(4, 64, 1), 128, smem64>>>(
        hbuf, w2, b2, x, y, nullptr,
        MROWS, DM, DFFN, 0, 0, 0, 1.f, 0, 0);

    // 10) LN2 -> out
    ln_kernel<<<MROWS, 256>>>(y, g2, be2, out);
}

// round 12
// speedup vs baseline: 1.3803x; 1.3803x over previous
#include <cuda_runtime.h>
#include <stdint.h>
#include <math.h>

#define BD    4
#define NSEQ  1024
#define DM    256
#define NH    8
#define HD    32
#define DFFN  1024
#define MROWS (BD * NSEQ)   // 4096
#define NQKV  768

// ---------------- static scratch ----------------
__device__ float g_qkin[MROWS * DM];        // embed + query_pos
__device__ float g_qkv[MROWS * NQKV];       // [4096, 768]: q | k | v
__device__ float g_tau[BD * NH * NSEQ];     // [B, H, N]
__device__ float g_ctx[MROWS * DM];
__device__ float g_y[MROWS * DM];
__device__ float g_x[MROWS * DM];
__device__ float g_h[MROWS * DFFN];

// ---------------- helpers ----------------
__device__ __forceinline__ unsigned f2tf(float f)
{
    unsigned u;
    asm("cvt.rna.tf32.f32 %0, %1;" : "=r"(u) : "f"(f));
    return u;
}

__device__ __forceinline__ void cp16(float* dst, const float* src)
{
    unsigned d = (unsigned)__cvta_generic_to_shared(dst);
    asm volatile("cp.async.cg.shared.global [%0], [%1], 16;" :: "r"(d), "l"(src));
}

#define CP_COMMIT() asm volatile("cp.async.commit_group;")

#define MMA_TF32(d, a, b0, b1)                                              \
    asm volatile("mma.sync.aligned.m16n8k8.row.col.f32.tf32.tf32.f32 "      \
                 "{%0,%1,%2,%3}, {%4,%5,%6,%7}, {%8,%9}, {%0,%1,%2,%3};"    \
                 : "+f"((d)[0]), "+f"((d)[1]), "+f"((d)[2]), "+f"((d)[3])   \
                 : "r"((a)[0]), "r"((a)[1]), "r"((a)[2]), "r"((a)[3]),      \
                   "r"(b0), "r"(b1))

// ---------------- elementwise: qk = embed + query_pos ----------------
__global__ void add_pos_kernel(const float4* __restrict__ a,
                               const float4* __restrict__ b,
                               float4* __restrict__ o)
{
    int i = blockIdx.x * blockDim.x + threadIdx.x;
    float4 x = a[i], y = b[i];
    o[i] = make_float4(x.x + y.x, x.y + y.y, x.z + y.z, x.w + y.w);
}

// ---------------- tau ----------------
__global__ void tau_kernel(const float* __restrict__ embed,
                           const float* __restrict__ tw,
                           const float* __restrict__ tb,
                           float* __restrict__ tau)
{
    int warp_id = (blockIdx.x * blockDim.x + threadIdx.x) >> 5;
    int lane = threadIdx.x & 31;
    const float* er = embed + (size_t)warp_id * DM;
    float ph[NH];
    #pragma unroll
    for (int h = 0; h < NH; h++) ph[h] = 0.f;
    #pragma unroll
    for (int t = 0; t < 8; t++) {
        int d = lane + t * 32;
        float e = er[d];
        #pragma unroll
        for (int h = 0; h < NH; h++) ph[h] += e * tw[h * DM + d];
    }
    #pragma unroll
    for (int h = 0; h < NH; h++) {
        float v = ph[h];
        #pragma unroll
        for (int o = 16; o > 0; o >>= 1) v += __shfl_xor_sync(0xffffffffu, v, o);
        if (lane == 0) {
            int b = warp_id >> 10, n = warp_id & 1023;
            tau[((size_t)b * NH + h) * NSEQ + n] = v + tb[h];
        }
    }
}

// ---------------- async tile loader for GEMM ----------------
template<int BM>
__device__ __forceinline__ void gemm_load(const float* __restrict__ Ag,
                                          const float* __restrict__ Wg,
                                          float* sA, float* sB, int tid, int K)
{
    constexpr int T = BM * 2;
    #pragma unroll
    for (int i = 0; i < (BM * 8) / T; i++) {
        int idx = tid + i * T;
        int row = idx >> 3, c4 = (idx & 7) << 2;
        cp16(sA + row * 36 + c4, Ag + (size_t)row * K + c4);
    }
    #pragma unroll
    for (int i = 0; i < 512 / T; i++) {
        int idx = tid + i * T;
        int row = idx >> 3, c4 = (idx & 7) << 2;
        cp16(sB + row * 36 + c4, Wg + (size_t)row * K + c4);
    }
    CP_COMMIT();
}

// ---------------- tf32 tensor-core GEMM (double-buffered cp.async) ----------------
template<int BM>
__global__ void gemm_tc(const float* __restrict__ A, const float* __restrict__ A2,
                        const float* __restrict__ W, const float* __restrict__ bias,
                        const float* __restrict__ resid, float* __restrict__ C,
                        int M, int N, int K, int doRelu, int nsplit)
{
    extern __shared__ float smem[];
    constexpr int STAGE = (BM + 64) * 36;
    int tid = threadIdx.x, lane = tid & 31, wid = tid >> 5;
    int m0 = blockIdx.y * BM, n0 = blockIdx.x * 64;
    const float* Ause = (n0 >= nsplit) ? A2 : A;
    const float* Abase = Ause + (size_t)m0 * K;
    const float* Wbase = W + (size_t)n0 * K;
    int nk = K >> 5;

    constexpr int WMN = BM / 32;
    int wm = (wid % WMN) * 32, wn = (wid / WMN) * 32;
    int gr = lane >> 2, gq = lane & 3;

    gemm_load<BM>(Abase, Wbase, smem, smem + BM * 36, tid, K);

    float acc[2][4][4];
    #pragma unroll
    for (int mi = 0; mi < 2; mi++)
        #pragma unroll
        for (int ni = 0; ni < 4; ni++)
            #pragma unroll
            for (int k = 0; k < 4; k++) acc[mi][ni][k] = 0.f;

    for (int kt = 0; kt < nk; kt++) {
        float* cur = smem + (kt & 1) * STAGE;
        float* nxt = smem + ((kt + 1) & 1) * STAGE;
        if (kt + 1 < nk) {
            gemm_load<BM>(Abase + (kt + 1) * 32, Wbase + (kt + 1) * 32,
                          nxt, nxt + BM * 36, tid, K);
            asm volatile("cp.async.wait_group 1;");
        } else {
            asm volatile("cp.async.wait_group 0;");
        }
        __syncthreads();
        const float* cA = cur;
        const float* cB = cur + BM * 36;
        #pragma unroll
        for (int k0 = 0; k0 < 32; k0 += 8) {
            unsigned af[2][4], bf[4][2];
            #pragma unroll
            for (int mi = 0; mi < 2; mi++) {
                int r = wm + mi * 16 + gr, c = k0 + gq;
                af[mi][0] = __float_as_uint(cA[r * 36 + c]);
                af[mi][1] = __float_as_uint(cA[(r + 8) * 36 + c]);
                af[mi][2] = __float_as_uint(cA[r * 36 + c + 4]);
                af[mi][3] = __float_as_uint(cA[(r + 8) * 36 + c + 4]);
            }
            #pragma unroll
            for (int ni = 0; ni < 4; ni++) {
                int cc = wn + ni * 8 + gr;
                bf[ni][0] = __float_as_uint(cB[cc * 36 + k0 + gq]);
                bf[ni][1] = __float_as_uint(cB[cc * 36 + k0 + 4 + gq]);
            }
            #pragma unroll
            for (int mi = 0; mi < 2; mi++)
                #pragma unroll
                for (int ni = 0; ni < 4; ni++)
                    MMA_TF32(acc[mi][ni], af[mi], bf[ni][0], bf[ni][1]);
        }
        __syncthreads();
    }

    #pragma unroll
    for (int mi = 0; mi < 2; mi++) {
        #pragma unroll
        for (int ni = 0; ni < 4; ni++) {
            int r = m0 + wm + mi * 16 + gr;
            int c = n0 + wn + ni * 8 + 2 * gq;
            float2 bb = *(const float2*)(bias + c);
            float v0 = acc[mi][ni][0] + bb.x, v1 = acc[mi][ni][1] + bb.y;
            float v2 = acc[mi][ni][2] + bb.x, v3 = acc[mi][ni][3] + bb.y;
            if (doRelu) {
                v0 = fmaxf(v0, 0.f); v1 = fmaxf(v1, 0.f);
                v2 = fmaxf(v2, 0.f); v3 = fmaxf(v3, 0.f);
            }
            if (resid) {
                float2 r0v = *(const float2*)(resid + (size_t)r * N + c);
                float2 r1v = *(const float2*)(resid + (size_t)(r + 8) * N + c);
                v0 += r0v.x; v1 += r0v.y; v2 += r1v.x; v3 += r1v.y;
            }
            *(float2*)(C + (size_t)r * N + c) = make_float2(v0, v1);
            *(float2*)(C + (size_t)(r + 8) * N + c) = make_float2(v2, v3);
        }
    }
}

// ---------------- attention smem geometry ----------------
//  K stride 36: QK B-frag bank = (4*gr + gq) % 32  -> 32 distinct
//  V stride 40: PV B-frag bank = (8*gq + gr + 8ni) % 32 -> 32 distinct
//  P stride 68: PV A-frag bank = (4*gr + gq) % 32  -> 32 distinct
//  Osum stride 34 (even!) so float2 accesses stay 8-byte aligned
#define KSS   36
#define VSS   40
#define QSS   36
#define PPS   68
#define OSS   34
#define KVST  (64 * KSS + 64 * VSS)     // one stage = 4864 floats
#define OFF_STAT (2 * KVST)             // pmax[2][64], psum[2][64]
#define OFF_PS   (OFF_STAT + 256)       // 64 x PPS (aliases Q staging)
#define SMEM_ATT ((OFF_PS + 64 * PPS) * 4)

// K/V async loader: 64 rows x 32 floats each, 256 threads
__device__ __forceinline__ void attn_load(const float* __restrict__ kbase,
                                          const float* __restrict__ vbase,
                                          float* stage, int tid)
{
    float* sK = stage;
    float* sV = stage + 64 * KSS;
    #pragma unroll
    for (int i = 0; i < 2; i++) {
        int idx = tid + i * 256;
        int row = idx >> 3, c4 = (idx & 7) << 2;
        cp16(sK + row * KSS + c4, kbase + (size_t)row * NQKV + c4);
        cp16(sV + row * VSS + c4, vbase + (size_t)row * NQKV + c4);
    }
    CP_COMMIT();
}

// ---------------- tf32 flash attention: 64 q-rows, 8 warps (4m x 2n) ----------------
__global__ __launch_bounds__(256, 3)
void attn_tc(const float* __restrict__ qkv, const float* __restrict__ dist,
             const float* __restrict__ tau, float* __restrict__ ctx)
{
    extern __shared__ float sm[];
    float* pmax = sm + OFF_STAT;        // [2][64]
    float* psum = pmax + 128;           // [2][64]
    float* Ps   = sm + OFF_PS;          // 64 x PPS

    int b = blockIdx.z, h = blockIdx.y, i0 = blockIdx.x * 64;
    int tid = threadIdx.x, lane = tid & 31, wid = tid >> 5;
    int wm = wid & 3, wn = wid >> 2;
    int gr = lane >> 2, gq = lane & 3;
    int wr = wm * 16;

    const float sc = 0.17677669529663687f;  // 1/sqrt(32)

    // ---- stage Q (scaled, tf32) at stride QSS inside Ps buffer, lift A-frags
    #pragma unroll
    for (int i = 0; i < 2; i++) {
        int idx = tid + i * 256;
        int row = idx >> 3, c = (idx & 7) << 2;
        float4 q = *(const float4*)(qkv + (size_t)(b * NSEQ + i0 + row) * NQKV + h * 32 + c);
        Ps[row * QSS + c]     = __uint_as_float(f2tf(q.x * sc));
        Ps[row * QSS + c + 1] = __uint_as_float(f2tf(q.y * sc));
        Ps[row * QSS + c + 2] = __uint_as_float(f2tf(q.z * sc));
        Ps[row * QSS + c + 3] = __uint_as_float(f2tf(q.w * sc));
    }
    __syncthreads();
    unsigned qf[4][4];
    #pragma unroll
    for (int k8 = 0; k8 < 4; k8++) {
        int c = k8 * 8 + gq;
        qf[k8][0] = __float_as_uint(Ps[(wr + gr) * QSS + c]);
        qf[k8][1] = __float_as_uint(Ps[(wr + 8 + gr) * QSS + c]);
        qf[k8][2] = __float_as_uint(Ps[(wr + gr) * QSS + c + 4]);
        qf[k8][3] = __float_as_uint(Ps[(wr + 8 + gr) * QSS + c + 4]);
    }
    __syncthreads();

    const float* kbase = qkv + (size_t)(b * NSEQ) * NQKV + 256 + h * 32;
    const float* vbase = qkv + (size_t)(b * NSEQ) * NQKV + 512 + h * 32;
    attn_load(kbase, vbase, sm, tid);

    int r0 = wr + gr, r1 = wr + 8 + gr;
    float tv0 = tau[((size_t)b * NH + h) * NSEQ + i0 + r0];
    float tv1 = tau[((size_t)b * NH + h) * NSEQ + i0 + r1];
    const float* dp0 = dist + ((size_t)b * NSEQ + i0 + r0) * NSEQ + wn * 32;
    const float* dp1 = dist + ((size_t)b * NSEQ + i0 + r1) * NSEQ + wn * 32;

    float mr0 = -1e30f, mr1 = -1e30f, lr0 = 0.f, lr1 = 0.f;
    float o[4][4];
    #pragma unroll
    for (int ni = 0; ni < 4; ni++)
        #pragma unroll
        for (int k = 0; k < 4; k++) o[ni][k] = 0.f;

    for (int jt = 0; jt < NSEQ / 64; jt++) {
        float* cur = sm + (jt & 1) * KVST;
        float* nxt = sm + ((jt + 1) & 1) * KVST;
        if (jt + 1 < NSEQ / 64) {
            attn_load(kbase + (size_t)(jt + 1) * 64 * NQKV,
                      vbase + (size_t)(jt + 1) * 64 * NQKV, nxt, tid);
            asm volatile("cp.async.wait_group 1;");
        } else {
            asm volatile("cp.async.wait_group 0;");
        }
        __syncthreads();                               // [S1] KV visible
        const float* Ks = cur;
        const float* Vs = cur + 64 * KSS;

        // ---- S quadrant: rows wr.., cols wn*32 + ni*8
        float s[4][4];
        #pragma unroll
        for (int ni = 0; ni < 4; ni++)
            #pragma unroll
            for (int k = 0; k < 4; k++) s[ni][k] = 0.f;

        #pragma unroll
        for (int k8 = 0; k8 < 4; k8++) {
            int c = k8 * 8 + gq;
            unsigned bf[4][2];
            #pragma unroll
            for (int ni = 0; ni < 4; ni++) {
                int jj = wn * 32 + ni * 8 + gr;
                bf[ni][0] = __float_as_uint(Ks[jj * KSS + c]);
                bf[ni][1] = __float_as_uint(Ks[jj * KSS + c + 4]);
            }
            #pragma unroll
            for (int ni = 0; ni < 4; ni++)
                MMA_TF32(s[ni], qf[k8], bf[ni][0], bf[ni][1]);
        }

        // ---- bias + partial max
        float tm0 = -1e30f, tm1 = -1e30f;
        #pragma unroll
        for (int ni = 0; ni < 4; ni++) {
            int jc = jt * 64 + ni * 8 + 2 * gq;        // dp already offset by wn*32
            float2 dA = *(const float2*)(dp0 + jc);
            float2 dB = *(const float2*)(dp1 + jc);
            s[ni][0] += dA.x * tv0;
            s[ni][1] += dA.y * tv0;
            s[ni][2] += dB.x * tv1;
            s[ni][3] += dB.y * tv1;
            tm0 = fmaxf(tm0, fmaxf(s[ni][0], s[ni][1]));
            tm1 = fmaxf(tm1, fmaxf(s[ni][2], s[ni][3]));
        }
        tm0 = fmaxf(tm0, __shfl_xor_sync(0xffffffffu, tm0, 1));
        tm0 = fmaxf(tm0, __shfl_xor_sync(0xffffffffu, tm0, 2));
        tm1 = fmaxf(tm1, __shfl_xor_sync(0xffffffffu, tm1, 1));
        tm1 = fmaxf(tm1, __shfl_xor_sync(0xffffffffu, tm1, 2));
        if (gq == 0) {
            pmax[wn * 64 + r0] = tm0;
            pmax[wn * 64 + r1] = tm1;
        }
        __syncthreads();                               // [S2] stats half 1

        float mn0 = fmaxf(mr0, fmaxf(pmax[r0], pmax[64 + r0]));
        float mn1 = fmaxf(mr1, fmaxf(pmax[r1], pmax[64 + r1]));
        float cor0 = __expf(mr0 - mn0), cor1 = __expf(mr1 - mn1);
        mr0 = mn0; mr1 = mn1;

        float ps0 = 0.f, ps1 = 0.f;
        #pragma unroll
        for (int ni = 0; ni < 4; ni++) {
            s[ni][0] = __expf(s[ni][0] - mn0);
            s[ni][1] = __expf(s[ni][1] - mn0);
            s[ni][2] = __expf(s[ni][2] - mn1);
            s[ni][3] = __expf(s[ni][3] - mn1);
            ps0 += s[ni][0] + s[ni][1];
            ps1 += s[ni][2] + s[ni][3];
        }
        ps0 += __shfl_xor_sync(0xffffffffu, ps0, 1);
        ps0 += __shfl_xor_sync(0xffffffffu, ps0, 2);
        ps1 += __shfl_xor_sync(0xffffffffu, ps1, 1);
        ps1 += __shfl_xor_sync(0xffffffffu, ps1, 2);
        if (gq == 0) {
            psum[wn * 64 + r0] = ps0;
            psum[wn * 64 + r1] = ps1;
        }

        // ---- stage P strip (warp-private) with 64-bit stores
        #pragma unroll
        for (int ni = 0; ni < 4; ni++) {
            int jc = wn * 32 + ni * 8 + 2 * gq;
            *(float2*)&Ps[r0 * PPS + jc] = make_float2(s[ni][0], s[ni][1]);
            *(float2*)&Ps[r1 * PPS + jc] = make_float2(s[ni][2], s[ni][3]);
        }
        __syncthreads();                               // [S3] stats half 2 + P ordered

        lr0 = lr0 * cor0 + psum[r0] + psum[64 + r0];
        lr1 = lr1 * cor1 + psum[r1] + psum[64 + r1];
        #pragma unroll
        for (int ni = 0; ni < 4; ni++) {
            o[ni][0] *= cor0; o[ni][1] *= cor0;
            o[ni][2] *= cor1; o[ni][3] *= cor1;
        }

        // ---- partial O += P[:, wn-half] @ V[wn-half, :]
        #pragma unroll
        for (int k8 = 0; k8 < 4; k8++) {
            int c = (wn * 4 + k8) * 8 + gq;
            unsigned af[4], bf[4][2];
            af[0] = __float_as_uint(Ps[r0 * PPS + c]);
            af[1] = __float_as_uint(Ps[r1 * PPS + c]);
            af[2] = __float_as_uint(Ps[r0 * PPS + c + 4]);
            af[3] = __float_as_uint(Ps[r1 * PPS + c + 4]);
            #pragma unroll
            for (int ni = 0; ni < 4; ni++) {
                bf[ni][0] = __float_as_uint(Vs[c * VSS + ni * 8 + gr]);
                bf[ni][1] = __float_as_uint(Vs[(c + 4) * VSS + ni * 8 + gr]);
            }
            #pragma unroll
            for (int ni = 0; ni < 4; ni++)
                MMA_TF32(o[ni], af, bf[ni][0], bf[ni][1]);
        }
        if (jt + 1 < NSEQ / 64)
            __syncthreads();                           // [S4] protect cur for next prefetch
    }

    // ---- combine the two k-half partial Os via stage-0 smem (free after last tile)
    float* Osum = sm;                                  // 64 x OSS (last tile used stage 1)
    if (wn == 0) {
        #pragma unroll
        for (int ni = 0; ni < 4; ni++) {
            int d = ni * 8 + 2 * gq;
            *(float2*)&Osum[r0 * OSS + d] = make_float2(o[ni][0], o[ni][1]);
            *(float2*)&Osum[r1 * OSS + d] = make_float2(o[ni][2], o[ni][3]);
        }
    }
    __syncthreads();
    if (wn == 1) {
        float il0 = 1.f / lr0, il1 = 1.f / lr1;
        size_t gA = (size_t)(b * NSEQ + i0 + r0) * 256 + h * 32;
        size_t gB = (size_t)(b * NSEQ + i0 + r1) * 256 + h * 32;
        #pragma unroll
        for (int ni = 0; ni < 4; ni++) {
            int d = ni * 8 + 2 * gq;
            float2 pA = *(const float2*)&Osum[r0 * OSS + d];
            float2 pB = *(const float2*)&Osum[r1 * OSS + d];
            float a0 = (pA.x + o[ni][0]) * il0;
            float a1 = (pA.y + o[ni][1]) * il0;
            float a2 = (pB.x + o[ni][2]) * il1;
            float a3 = (pB.y + o[ni][3]) * il1;
            *(float2*)(ctx + gA + d) = make_float2(a0, a1);
            *(float2*)(ctx + gB + d) = make_float2(a2, a3);
        }
    }
}

// ---------------- row LayerNorm ----------------
__global__ void ln_kernel(const float* __restrict__ in, const float* __restrict__ g,
                          const float* __restrict__ bt, float* __restrict__ out)
{
    int row = blockIdx.x, t = threadIdx.x;
    float v = in[(size_t)row * DM + t];
    float s = v, s2 = v * v;
    #pragma unroll
    for (int o = 16; o > 0; o >>= 1) {
        s  += __shfl_xor_sync(0xffffffffu, s, o);
        s2 += __shfl_xor_sync(0xffffffffu, s2, o);
    }
    __shared__ float rs[8], rs2[8];
    __shared__ float mu_s, rstd_s;
    int w = t >> 5, lane = t & 31;
    if (lane == 0) { rs[w] = s; rs2[w] = s2; }
    __syncthreads();
    if (t == 0) {
        float a = 0.f, b2 = 0.f;
        #pragma unroll
        for (int i = 0; i < 8; i++) { a += rs[i]; b2 += rs2[i]; }
        float mu = a * (1.f / 256.f);
        float var = b2 * (1.f / 256.f) - mu * mu;
        mu_s = mu;
        rstd_s = rsqrtf(var + 1e-5f);
    }
    __syncthreads();
    out[(size_t)row * DM + t] = (v - mu_s) * rstd_s * g[t] + bt[t];
}

// ---------------- launch ----------------
static float* sym_addr(const void* sym)
{
    void* p = nullptr;
    cudaGetSymbolAddress(&p, sym);
    return (float*)p;
}

extern "C" void kernel_launch(void* const* d_in, const int* in_sizes, int n_in,
                              void* d_out, int out_size)
{
    const float* embed = (const float*)d_in[0];
    const float* dist  = (const float*)d_in[2];
    const float* qpos  = (const float*)d_in[3];
    const float* inw   = (const float*)d_in[4];
    const float* inb   = (const float*)d_in[5];
    const float* outw  = (const float*)d_in[6];
    const float* outb  = (const float*)d_in[7];
    const float* tauw  = (const float*)d_in[8];
    const float* taub  = (const float*)d_in[9];
    const float* w1    = (const float*)d_in[10];
    const float* b1    = (const float*)d_in[11];
    const float* w2    = (const float*)d_in[12];
    const float* b2    = (const float*)d_in[13];
    const float* g1    = (const float*)d_in[14];
    const float* be1   = (const float*)d_in[15];
    const float* g2    = (const float*)d_in[16];
    const float* be2   = (const float*)d_in[17];
    float* out = (float*)d_out;

    float* qkin = sym_addr(g_qkin);
    float* qkv  = sym_addr(g_qkv);
    float* tau  = sym_addr(g_tau);
    float* ctx  = sym_addr(g_ctx);
    float* y    = sym_addr(g_y);
    float* x    = sym_addr(g_x);
    float* hbuf = sym_addr(g_h);

    const int smem128 = 2 * (128 + 64) * 36 * 4;   // 55296
    const int smem64  = 2 * (64 + 64) * 36 * 4;    // 36864

    cudaFuncSetAttribute(gemm_tc<128>, cudaFuncAttributeMaxDynamicSharedMemorySize, smem128);
    cudaFuncSetAttribute(gemm_tc<64>,  cudaFuncAttributeMaxDynamicSharedMemorySize, smem64);
    cudaFuncSetAttribute(attn_tc,      cudaFuncAttributeMaxDynamicSharedMemorySize, SMEM_ATT);

    // 1) qk = embed + query_pos
    add_pos_kernel<<<(MROWS * DM / 4) / 256, 256>>>(
        (const float4*)embed, (const float4*)qpos, (float4*)qkin);

    // 2) tau
    tau_kernel<<<512, 256>>>(embed, tauw, taub, tau);

    // 3) fused QKV projection
    gemm_tc<128><<<dim3(NQKV / 64, MROWS / 128), 256, smem128>>>(
        qkin, embed, inw, inb, nullptr, qkv, MROWS, NQKV, DM, 0, 512);

    // 4) attention (64 q-rows, 8 warps)
    attn_tc<<<dim3(NSEQ / 64, NH, BD), 256, SMEM_ATT>>>(qkv, dist, tau, ctx);

    // 5) out projection + residual(embed)
    gemm_tc<64><<<dim3(DM / 64, MROWS / 64), 128, smem64>>>(
        ctx, ctx, outw, outb, embed, y, MROWS, DM, DM, 0, 1 << 30);

    // 6) LN1
    ln_kernel<<<MROWS, 256>>>(y, g1, be1, x);

    // 7) FFN1 + ReLU
    gemm_tc<128><<<dim3(DFFN / 64, MROWS / 128), 256, smem128>>>(
        x, x, w1, b1, nullptr, hbuf, MROWS, DFFN, DM, 1, 1 << 30);

    // 8) FFN2 + residual(x)
    gemm_tc<64><<<dim3(DM / 64, MROWS / 64), 128, smem64>>>(
        hbuf, hbuf, w2, b2, x, y, MROWS, DM, DFFN, 0, 1 << 30);

    // 9) LN2 -> out
    ln_kernel<<<MROWS, 256>>>(y, g2, be2, out);
}